// round 14
// baseline (speedup 1.0000x reference)
#include <cuda_runtime.h>
#include <cuda_fp16.h>
#include <cstdint>

#define NDIM   32
#define DDIM   256
#define HDIM   1024
#define HC     128
#define NCHUNK 8
#define THREADS 384

// smem layout (bytes) — XOR-swizzled packed tiles (R7-proven patterns)
#define S_XH   0        // fp16 [32][512B]   16384
#define S_PS   16384    // 3 x [32][512B]    49152   (P; front 8KB doubles as h1)
#define PS_BUF 16384
#define S_HS   65536    // 3 x [32][256B]    24576   (h0)
#define HS_BUF 8192
#define S_W1   90112    // [256 d][256B]     65536
#define S_W2   155648   // [128 h][512B]     65536
#define SMEM_TOTAL 221184

__device__ __forceinline__ unsigned smem_u32(const void* p) {
    unsigned a;
    asm("{ .reg .u64 t; cvta.to.shared.u64 t, %1; cvt.u32.u64 %0, t; }" : "=r"(a) : "l"(p));
    return a;
}
__device__ __forceinline__ void ldsm4(unsigned r[4], unsigned a) {
    asm volatile("ldmatrix.sync.aligned.m8n8.x4.shared.b16 {%0,%1,%2,%3}, [%4];\n"
                 : "=r"(r[0]), "=r"(r[1]), "=r"(r[2]), "=r"(r[3]) : "r"(a));
}
__device__ __forceinline__ void ldsm4t(unsigned r[4], unsigned a) {
    asm volatile("ldmatrix.sync.aligned.m8n8.x4.trans.shared.b16 {%0,%1,%2,%3}, [%4];\n"
                 : "=r"(r[0]), "=r"(r[1]), "=r"(r[2]), "=r"(r[3]) : "r"(a));
}
__device__ __forceinline__ void mma16816(float d[4], const unsigned a[4],
                                         unsigned b0, unsigned b1) {
    asm volatile("mma.sync.aligned.m16n8k16.row.col.f32.f16.f16.f32 "
                 "{%0,%1,%2,%3}, {%4,%5,%6,%7}, {%8,%9}, {%0,%1,%2,%3};\n"
                 : "+f"(d[0]), "+f"(d[1]), "+f"(d[2]), "+f"(d[3])
                 : "r"(a[0]), "r"(a[1]), "r"(a[2]), "r"(a[3]), "r"(b0), "r"(b1));
}
__device__ __forceinline__ unsigned hmul2u(unsigned a, unsigned b) {
    __half2 r = __hmul2(*(__half2*)&a, *(__half2*)&b);
    return *(unsigned*)&r;
}
__device__ __forceinline__ unsigned f2h2u(float x, float y) {
    __half2 h = __floats2half2_rn(x, y);
    return *(unsigned*)&h;
}

__global__ __launch_bounds__(THREADS, 1)
void fused_pair_mlp_v7(const float* __restrict__ X,  const float* __restrict__ W1g,
                       const float* __restrict__ b1g, const float* __restrict__ W2g,
                       const float* __restrict__ b2g, float* __restrict__ out)
{
    extern __shared__ unsigned char smem[];
    const int b = blockIdx.x, tid = threadIdx.x;
    const int w = tid >> 5, lane = tid & 31;
    const int g = w >> 2, wg = w & 3;
    const int gtid = tid & 127;
    const int gid = lane >> 2, tig = lane & 3;

    // ldmatrix lane mapping + swizzle key (R7-proven)
    const int mat = lane >> 3, mr = lane & 7;
    const int lrow = (mat & 1) * 8 + mr;
    const int kb = mat >> 1;
    const int xr = lrow & 7;

    const unsigned sb = smem_u32(smem);
    unsigned char* Pb = smem + S_PS + g * PS_BUF;
    unsigned char* Hb0 = smem + S_HS + g * HS_BUF;

    const unsigned uP  = sb + S_PS + (unsigned)(g * PS_BUF);
    const unsigned b1a = sb + S_W1 + (unsigned)(lrow * 256) + ((((unsigned)(4 * wg + kb)) ^ xr) << 4);
    const unsigned b1b = sb + S_W1 + (unsigned)(lrow * 256) + ((((unsigned)(4 * wg + 2 + kb)) ^ xr) << 4);
    unsigned b2x[4];
    #pragma unroll
    for (int n = 0; n < 4; ++n)
        b2x[n] = sb + S_W2 + (unsigned)(lrow * 512) + ((((unsigned)(8 * wg + 2 * n + kb)) ^ xr) << 4);
    const unsigned aH0 = sb + S_HS + (unsigned)(g * HS_BUF) + (unsigned)(lrow * 256);
    const unsigned aH1 = uP + (unsigned)(lrow * 256);   // h1 lives in P buffer front

    // ---- stage X_b fp16, [32][512B] XOR-swizzled (conflict-free)
    for (int q = tid; q < 1024; q += THREADS) {
        int row = q >> 5, u = q & 31;
        const float4* s = (const float4*)(X + (size_t)b * 8192 + row * 256 + u * 8);
        float4 v0 = s[0], v1 = s[1];
        *(uint4*)(smem + S_XH + row * 512 + (u >> 3) * 128 + (((u & 7) ^ (row & 7)) << 4)) =
            make_uint4(f2h2u(v0.x, v0.y), f2h2u(v0.z, v0.w),
                       f2h2u(v1.x, v1.y), f2h2u(v1.z, v1.w));
    }

    // P-build mapping: lane -> row, warp-in-group -> 128B slice (conflict-free phases)
    const int pj = lane, ps = gtid >> 5;
    const int pj7 = pj & 7;
    const unsigned xjb = (unsigned)(pj * 512 + ps * 128);

    // persistent out accumulator: warp owns out cols [64wg, 64wg+64)
    float oacc[2][8][4];
    #pragma unroll
    for (int m = 0; m < 2; ++m)
        #pragma unroll
        for (int t = 0; t < 8; ++t)
            #pragma unroll
            for (int r = 0; r < 4; ++r) oacc[m][t][r] = 0.f;

    for (int c = 0; c < NCHUNK; ++c) {
        __syncthreads();  // prev chunk readers done
        // ---- stage W1 chunk [256 d][128 hc], XOR-swizzled 256B rows
        for (int q = tid; q < 4096; q += THREADS) {
            int d = q >> 4, f = q & 15;
            const float* s = W1g + (size_t)d * HDIM + c * HC + f * 8;
            float4 v0 = *(const float4*)s, v1 = *(const float4*)(s + 4);
            *(uint4*)(smem + S_W1 + d * 256 + ((f ^ (d & 7)) << 4)) =
                make_uint4(f2h2u(v0.x, v0.y), f2h2u(v0.z, v0.w),
                           f2h2u(v1.x, v1.y), f2h2u(v1.z, v1.w));
        }
        // ---- stage W2 chunk [128 hc][256 d], XOR-swizzled 512B rows
        for (int q = tid; q < 4096; q += THREADS) {
            int h = q >> 5, f = q & 31;
            const float* s = W2g + (size_t)(c * HC + h) * DDIM + f * 8;
            float4 v0 = *(const float4*)s, v1 = *(const float4*)(s + 4);
            *(uint4*)(smem + S_W2 + h * 512 + ((f ^ (h & 7)) << 4)) =
                make_uint4(f2h2u(v0.x, v0.y), f2h2u(v0.z, v0.w),
                           f2h2u(v1.x, v1.y), f2h2u(v1.z, v1.w));
        }
        float b1v[4][2];
        #pragma unroll
        for (int t = 0; t < 4; ++t) {
            b1v[t][0] = __ldg(b1g + c * HC + 32 * wg + 8 * t + 2 * tig);
            b1v[t][1] = __ldg(b1g + c * HC + 32 * wg + 8 * t + 2 * tig + 1);
        }
        __syncthreads();  // W chunk ready

        for (int pp = 0; pp < 6; ++pp) {
            const int p = 3 * pp + g;       // pair index 0..15
            if (p >= 16) continue;          // uniform within group
            const int i0 = 2 * p, i1 = i0 + 1;

            asm volatile("bar.sync %0, %1;" :: "r"(1 + g), "r"(128));  // prev G2 h1-reads done

            float hacc[2][4][4];

            #pragma unroll
            for (int half = 0; half < 2; ++half) {
                const int i = half ? i1 : i0;
                // ---- build P_i[j,:] = xh[j] .* xh[i] (conflict-free, xi broadcast)
                {
                    const unsigned char* xsrc = smem + S_XH;
                    const unsigned char* xi = xsrc + i * 512 + ps * 128;
                    const int i7 = i & 7;
                    #pragma unroll
                    for (int u = 0; u < 8; ++u) {
                        uint4 a  = *(const uint4*)(xsrc + xjb + ((u ^ pj7) << 4));
                        uint4 c2 = *(const uint4*)(xi + ((u ^ i7) << 4));
                        uint4 o;
                        o.x = hmul2u(a.x, c2.x); o.y = hmul2u(a.y, c2.y);
                        o.z = hmul2u(a.z, c2.z); o.w = hmul2u(a.w, c2.w);
                        *(uint4*)(Pb + xjb + ((u ^ pj7) << 4)) = o;
                    }
                }
                asm volatile("bar.sync %0, %1;" :: "r"(1 + g), "r"(128));  // P ready

                // ---- GEMM1: h[32, 32wg..+32] = P @ W1c
                #pragma unroll
                for (int m = 0; m < 2; ++m)
                    #pragma unroll
                    for (int t = 0; t < 4; ++t)
                        #pragma unroll
                        for (int r = 0; r < 4; ++r) hacc[m][t][r] = 0.f;
                #pragma unroll 2
                for (int kk = 0; kk < 16; ++kk) {
                    unsigned off = ((((unsigned)(2 * kk + kb)) ^ xr) << 4);
                    unsigned A0[4], A1[4], B[8];
                    ldsm4(A0, uP + (unsigned)(lrow * 512) + off);
                    ldsm4(A1, uP + (unsigned)((lrow + 16) * 512) + off);
                    unsigned bk = (unsigned)(kk * 4096);
                    ldsm4t(B, b1a + bk);
                    ldsm4t(B + 4, b1b + bk);
                    #pragma unroll
                    for (int t = 0; t < 4; ++t) {
                        mma16816(hacc[0][t], A0, B[2 * t], B[2 * t + 1]);
                        mma16816(hacc[1][t], A1, B[2 * t], B[2 * t + 1]);
                    }
                }
                asm volatile("bar.sync %0, %1;" :: "r"(1 + g), "r"(128));  // P reads done

                // ---- bias + relu -> h0 to Hs, h1 to P-buf front (same pattern)
                unsigned char* Hd = half ? Pb : Hb0;
                #pragma unroll
                for (int m = 0; m < 2; ++m) {
                    #pragma unroll
                    for (int t = 0; t < 4; ++t) {
                        int r0 = 16 * m + gid;
                        unsigned un = ((unsigned)(4 * wg + t)) ^ (unsigned)(r0 & 7);
                        unsigned base = (unsigned)(r0 * 256) + (un << 4) + (unsigned)(4 * tig);
                        float f0 = fmaxf(hacc[m][t][0] + b1v[t][0], 0.f);
                        float f1 = fmaxf(hacc[m][t][1] + b1v[t][1], 0.f);
                        float f2 = fmaxf(hacc[m][t][2] + b1v[t][0], 0.f);
                        float f3 = fmaxf(hacc[m][t][3] + b1v[t][1], 0.f);
                        *(unsigned*)(Hd + base)        = f2h2u(f0, f1);
                        *(unsigned*)(Hd + base + 2048) = f2h2u(f2, f3);
                    }
                }
                if (half == 0) continue;  // proceed to build P(i1); h0 bar merges with P-ready bar
            }
            asm volatile("bar.sync %0, %1;" :: "r"(1 + g), "r"(128));  // h1 ready

            // ---- GEMM2 (shared B): oacc += h0 @ W2c + h1 @ W2c
            #pragma unroll 2
            for (int kk = 0; kk < 8; ++kk) {
                unsigned off = ((((unsigned)(2 * kk + kb)) ^ xr) << 4);
                unsigned A0[4], A1[4], Bb[8], Bc[8];
                unsigned bk = (unsigned)(kk * 8192);
                ldsm4t(Bb,     b2x[0] + bk);
                ldsm4t(Bb + 4, b2x[1] + bk);
                ldsm4t(Bc,     b2x[2] + bk);
                ldsm4t(Bc + 4, b2x[3] + bk);
                ldsm4(A0, aH0 + off);
                ldsm4(A1, aH0 + 4096u + off);
                #pragma unroll
                for (int t = 0; t < 4; ++t) {
                    mma16816(oacc[0][t],     A0, Bb[2 * t], Bb[2 * t + 1]);
                    mma16816(oacc[1][t],     A1, Bb[2 * t], Bb[2 * t + 1]);
                    mma16816(oacc[0][t + 4], A0, Bc[2 * t], Bc[2 * t + 1]);
                    mma16816(oacc[1][t + 4], A1, Bc[2 * t], Bc[2 * t + 1]);
                }
                ldsm4(A0, aH1 + off);
                ldsm4(A1, aH1 + 4096u + off);
                #pragma unroll
                for (int t = 0; t < 4; ++t) {
                    mma16816(oacc[0][t],     A0, Bb[2 * t], Bb[2 * t + 1]);
                    mma16816(oacc[1][t],     A1, Bb[2 * t], Bb[2 * t + 1]);
                    mma16816(oacc[0][t + 4], A0, Bc[2 * t], Bc[2 * t + 1]);
                    mma16816(oacc[1][t + 4], A1, Bc[2 * t], Bc[2 * t + 1]);
                }
            }
        }
    }

    // ---- epilogue: groups 1,2 dump to smem (X+P dead = 64KB); group 0 reduces
    __syncthreads();
    if (g > 0) {
        float* Os = (float*)(smem + (g - 1) * 32768);
        #pragma unroll
        for (int t = 0; t < 8; ++t) {
            int col = 64 * wg + 8 * t + 2 * tig;
            #pragma unroll
            for (int m = 0; m < 2; ++m) {
                int r0 = 16 * m + gid;
                *(float2*)(Os + r0 * DDIM + col)       = make_float2(oacc[m][t][0], oacc[m][t][1]);
                *(float2*)(Os + (r0 + 8) * DDIM + col) = make_float2(oacc[m][t][2], oacc[m][t][3]);
            }
        }
    }
    __syncthreads();
    if (g == 0) {
        float* Os1 = (float*)(smem);
        float* Os2 = (float*)(smem + 32768);
        float* og = out + (size_t)b * NDIM * DDIM;
        #pragma unroll
        for (int t = 0; t < 8; ++t) {
            int col = 64 * wg + 8 * t + 2 * tig;
            float bb0 = 32.0f * __ldg(b2g + col);
            float bb1 = 32.0f * __ldg(b2g + col + 1);
            #pragma unroll
            for (int m = 0; m < 2; ++m) {
                int r0 = 16 * m + gid;
                float2 s0 = *(float2*)(Os1 + r0 * DDIM + col);
                float2 s1 = *(float2*)(Os1 + (r0 + 8) * DDIM + col);
                float2 u0 = *(float2*)(Os2 + r0 * DDIM + col);
                float2 u1 = *(float2*)(Os2 + (r0 + 8) * DDIM + col);
                *(float2*)(og + (size_t)r0 * DDIM + col) =
                    make_float2(oacc[m][t][0] + s0.x + u0.x + bb0,
                                oacc[m][t][1] + s0.y + u0.y + bb1);
                *(float2*)(og + (size_t)(r0 + 8) * DDIM + col) =
                    make_float2(oacc[m][t][2] + s1.x + u1.x + bb0,
                                oacc[m][t][3] + s1.y + u1.y + bb1);
            }
        }
    }
}

extern "C" void kernel_launch(void* const* d_in, const int* in_sizes, int n_in,
                              void* d_out, int out_size) {
    (void)in_sizes; (void)n_in; (void)out_size;
    const float* X  = (const float*)d_in[0];   // [128,32,256]
    const float* W1 = (const float*)d_in[1];   // [256,1024]
    const float* b1 = (const float*)d_in[2];   // [1024]
    const float* W2 = (const float*)d_in[3];   // [1024,256]
    const float* b2 = (const float*)d_in[4];   // [256]
    float* out = (float*)d_out;                // [128,32,256]

    cudaFuncSetAttribute(fused_pair_mlp_v7,
                         cudaFuncAttributeMaxDynamicSharedMemorySize, SMEM_TOTAL);
    fused_pair_mlp_v7<<<128, THREADS, SMEM_TOTAL>>>(X, W1, b1, W2, b2, out);
}

// round 16
// speedup vs baseline: 1.6138x; 1.6138x over previous
#include <cuda_runtime.h>
#include <cuda_fp16.h>
#include <cstdint>

#define NDIM   32
#define DDIM   256
#define HDIM   1024
#define HC     128
#define NCHUNK 8
#define THREADS 384
#define NGROUP 3

// strides in halves (R5-proven conflict-free classes)
#define XH_H 264
#define PS_H 264
#define W1_H 136
#define W2_H 264
#define HS_H 136

// byte offsets
#define S_XH  0                      // fp16 [32][264]            16896
#define S_PS  16896                  // 3 x fp16 [32][264]        50688
#define PS_BUF 16896
#define S_W1  67584                  // fp16 [256][136]           69632
#define S_W2  137216                 // fp16 [128][264]           67584
#define S_HS  204800                 // 3 x fp16 [32][136]        26112
#define HS_BUF 8704
#define SMEM_TOTAL 230912

__device__ __forceinline__ unsigned smem_u32(const void* p) {
    unsigned a;
    asm("{ .reg .u64 t; cvta.to.shared.u64 t, %1; cvt.u32.u64 %0, t; }" : "=r"(a) : "l"(p));
    return a;
}
__device__ __forceinline__ void ldsm4(unsigned r[4], unsigned a) {
    asm volatile("ldmatrix.sync.aligned.m8n8.x4.shared.b16 {%0,%1,%2,%3}, [%4];\n"
                 : "=r"(r[0]), "=r"(r[1]), "=r"(r[2]), "=r"(r[3]) : "r"(a));
}
__device__ __forceinline__ void ldsm4t(unsigned r[4], unsigned a) {
    asm volatile("ldmatrix.sync.aligned.m8n8.x4.trans.shared.b16 {%0,%1,%2,%3}, [%4];\n"
                 : "=r"(r[0]), "=r"(r[1]), "=r"(r[2]), "=r"(r[3]) : "r"(a));
}
__device__ __forceinline__ void mma16816(float d[4], const unsigned a[4],
                                         unsigned b0, unsigned b1) {
    asm volatile("mma.sync.aligned.m16n8k16.row.col.f32.f16.f16.f32 "
                 "{%0,%1,%2,%3}, {%4,%5,%6,%7}, {%8,%9}, {%0,%1,%2,%3};\n"
                 : "+f"(d[0]), "+f"(d[1]), "+f"(d[2]), "+f"(d[3])
                 : "r"(a[0]), "r"(a[1]), "r"(a[2]), "r"(a[3]), "r"(b0), "r"(b1));
}
__device__ __forceinline__ unsigned hmul2u(unsigned a, unsigned b) {
    __half2 r = __hmul2(*(__half2*)&a, *(__half2*)&b);
    return *(unsigned*)&r;
}
__device__ __forceinline__ unsigned f2h2u(float x, float y) {
    __half2 h = __floats2half2_rn(x, y);
    return *(unsigned*)&h;
}

__global__ __launch_bounds__(THREADS, 1)
void fused_pair_mlp_v8(const float* __restrict__ X,  const float* __restrict__ W1g,
                       const float* __restrict__ b1g, const float* __restrict__ W2g,
                       const float* __restrict__ b2g, float* __restrict__ out)
{
    extern __shared__ unsigned char smem[];
    const int b = blockIdx.x, tid = threadIdx.x;
    const int w = tid >> 5, lane = tid & 31;
    const int g = w >> 2;          // 3 groups of 4 warps
    const int wg = w & 3;
    const int gtid = tid & 127;    // thread-in-group
    const int gid = lane >> 2, tig = lane & 3;

    unsigned char* Psp = smem + S_PS + g * PS_BUF;
    unsigned char* W1p = smem + S_W1;
    unsigned char* W2p = smem + S_W2;
    unsigned char* Hsp = smem + S_HS + g * HS_BUF;

    // ---- stage X_b as fp16 [32][264]
    for (int q = tid; q < 1024; q += THREADS) {
        int row = q >> 5, u = q & 31;
        const float4* s = (const float4*)(X + (size_t)b * 8192 + row * 256 + u * 8);
        float4 v0 = s[0], v1 = s[1];
        *(uint4*)(smem + S_XH + row * 528 + u * 16) =
            make_uint4(f2h2u(v0.x, v0.y), f2h2u(v0.z, v0.w),
                       f2h2u(v1.x, v1.y), f2h2u(v1.z, v1.w));
    }

    // ldmatrix per-lane address components (R5-identical)
    const int mat  = lane >> 3, mr = lane & 7;
    const int lrow = (mat & 1) * 8 + mr;
    const int kh   = (mat >> 1) * 8;

    const unsigned aA  = smem_u32(Psp) + (unsigned)(lrow * PS_H + kh) * 2u;
    const unsigned aB1 = smem_u32(W1p) + (unsigned)(lrow * W1_H + 32 * wg + kh) * 2u;
    const unsigned aH  = smem_u32(Hsp) + (unsigned)(lrow * HS_H + kh) * 2u;
    const unsigned aB2 = smem_u32(W2p) + (unsigned)(lrow * W2_H + 64 * wg + kh) * 2u;

    // P-build mapping (conflict-free): row = lane, 128B slice = warp-in-group.
    // bank-quad of xj-LDS/STS = (lane + k) mod 8 -> distinct within each
    // 8-lane phase group; xi is a pure warp broadcast.
    const int pj = lane, ps = gtid >> 5;

    // persistent out accumulator: warp owns out cols [64wg, 64wg+64)
    float oacc[2][8][4];
    #pragma unroll
    for (int m = 0; m < 2; ++m)
        #pragma unroll
        for (int t = 0; t < 8; ++t)
            #pragma unroll
            for (int r = 0; r < 4; ++r) oacc[m][t][r] = 0.f;

    for (int c = 0; c < NCHUNK; ++c) {
        __syncthreads();  // all readers of previous W chunk done

        // stage W1 chunk [256 d x 128 hc] -> half, stride 136
        for (int q = tid; q < 8192; q += THREADS) {
            int d = q >> 5, f = q & 31;
            float4 v = *(const float4*)(W1g + (size_t)d * HDIM + c * HC + f * 4);
            *(uint2*)(W1p + d * 272 + f * 8) =
                make_uint2(f2h2u(v.x, v.y), f2h2u(v.z, v.w));
        }
        // stage W2 chunk [128 hc x 256 d] -> half, stride 264
        for (int q = tid; q < 8192; q += THREADS) {
            int h = q >> 6, f = q & 63;
            float4 v = *(const float4*)(W2g + (size_t)(c * HC + h) * DDIM + f * 4);
            *(uint2*)(W2p + h * 528 + f * 8) =
                make_uint2(f2h2u(v.x, v.y), f2h2u(v.z, v.w));
        }
        float b1v[4][2];
        #pragma unroll
        for (int t = 0; t < 4; ++t) {
            b1v[t][0] = __ldg(b1g + c * HC + 32 * wg + 8 * t + 2 * tig);
            b1v[t][1] = __ldg(b1g + c * HC + 32 * wg + 8 * t + 2 * tig + 1);
        }
        __syncthreads();  // W chunk ready

        for (int ii = 0; ii < 11; ++ii) {
            const int i = NGROUP * ii + g;   // group-private i stream
            if (i < NDIM) {
                // ---- build P_i[j,:] = xh[j] .* xh[i]  (conflict-free mapping)
                {
                    const unsigned char* xj = smem + S_XH + pj * 528 + ps * 128;
                    const unsigned char* xi = smem + S_XH + i * 528 + ps * 128;
                    unsigned char* pd = Psp + pj * 528 + ps * 128;
                    #pragma unroll
                    for (int k = 0; k < 8; ++k) {
                        uint4 a  = *(const uint4*)(xj + k * 16);
                        uint4 c2 = *(const uint4*)(xi + k * 16);
                        uint4 o;
                        o.x = hmul2u(a.x, c2.x); o.y = hmul2u(a.y, c2.y);
                        o.z = hmul2u(a.z, c2.z); o.w = hmul2u(a.w, c2.w);
                        *(uint4*)(pd + k * 16) = o;
                    }
                }
                asm volatile("bar.sync %0, %1;" :: "r"(1 + g), "r"(128));  // P ready

                // ---- GEMM1: h[32, 32wg..+32] = P[32,256] @ W1[256, chunk]
                float hacc[2][4][4];
                #pragma unroll
                for (int m = 0; m < 2; ++m)
                    #pragma unroll
                    for (int t = 0; t < 4; ++t)
                        #pragma unroll
                        for (int r = 0; r < 4; ++r) hacc[m][t][r] = 0.f;
                #pragma unroll 2
                for (int kk = 0; kk < 16; ++kk) {
                    unsigned A0[4], A1[4], B[8];
                    unsigned ak = aA + (unsigned)(kk * 32);
                    ldsm4(A0, ak);
                    ldsm4(A1, ak + (unsigned)(16 * 528));
                    unsigned bk = aB1 + (unsigned)(kk * 16 * 272);
                    ldsm4t(B, bk);
                    ldsm4t(B + 4, bk + 32);
                    #pragma unroll
                    for (int t = 0; t < 4; ++t) {
                        mma16816(hacc[0][t], A0, B[2 * t], B[2 * t + 1]);
                        mma16816(hacc[1][t], A1, B[2 * t], B[2 * t + 1]);
                    }
                }

                // ---- bias + relu -> Hs (single buffer; safe by barrier order)
                #pragma unroll
                for (int m = 0; m < 2; ++m) {
                    #pragma unroll
                    for (int t = 0; t < 4; ++t) {
                        int col = 32 * wg + 8 * t + 2 * tig;
                        float f0 = fmaxf(hacc[m][t][0] + b1v[t][0], 0.f);
                        float f1 = fmaxf(hacc[m][t][1] + b1v[t][1], 0.f);
                        float f2 = fmaxf(hacc[m][t][2] + b1v[t][0], 0.f);
                        float f3 = fmaxf(hacc[m][t][3] + b1v[t][1], 0.f);
                        int r0 = 16 * m + gid;
                        *(unsigned*)(Hsp + r0 * 272 + col * 2)       = f2h2u(f0, f1);
                        *(unsigned*)(Hsp + (r0 + 8) * 272 + col * 2) = f2h2u(f2, f3);
                    }
                }
                asm volatile("bar.sync %0, %1;" :: "r"(1 + g), "r"(128));  // Hs ready

                // ---- GEMM2: oacc[32, 64wg..] += h[32,128] @ W2[128,256]
                #pragma unroll 2
                for (int kk = 0; kk < 8; ++kk) {
                    unsigned A0[4], A1[4], B[8];
                    unsigned ak = aH + (unsigned)(kk * 32);
                    ldsm4(A0, ak);
                    ldsm4(A1, ak + (unsigned)(16 * 272));
                    unsigned bk = aB2 + (unsigned)(kk * 16 * 528);
                    ldsm4t(B, bk);
                    ldsm4t(B + 4, bk + 32);
                    #pragma unroll
                    for (int t = 0; t < 4; ++t) {
                        mma16816(oacc[0][t], A0, B[2 * t], B[2 * t + 1]);
                        mma16816(oacc[1][t], A1, B[2 * t], B[2 * t + 1]);
                    }
                    ldsm4t(B, bk + 64);
                    ldsm4t(B + 4, bk + 96);
                    #pragma unroll
                    for (int t = 0; t < 4; ++t) {
                        mma16816(oacc[0][t + 4], A0, B[2 * t], B[2 * t + 1]);
                        mma16816(oacc[1][t + 4], A1, B[2 * t], B[2 * t + 1]);
                    }
                }
            }
        }
    }

    // ---- epilogue: groups 1,2 dump to smem; group 0 reduces + bias + store
    __syncthreads();
    if (g > 0) {
        float* Os = (float*)(smem + (g - 1) * 32768);   // X/P regions dead
        #pragma unroll
        for (int t = 0; t < 8; ++t) {
            int col = 64 * wg + 8 * t + 2 * tig;
            #pragma unroll
            for (int m = 0; m < 2; ++m) {
                int r0 = 16 * m + gid;
                *(float2*)(Os + r0 * DDIM + col)       = make_float2(oacc[m][t][0], oacc[m][t][1]);
                *(float2*)(Os + (r0 + 8) * DDIM + col) = make_float2(oacc[m][t][2], oacc[m][t][3]);
            }
        }
    }
    __syncthreads();
    if (g == 0) {
        float* Os1 = (float*)(smem);
        float* Os2 = (float*)(smem + 32768);
        float* og = out + (size_t)b * NDIM * DDIM;
        #pragma unroll
        for (int t = 0; t < 8; ++t) {
            int col = 64 * wg + 8 * t + 2 * tig;
            float bb0 = 32.0f * __ldg(b2g + col);
            float bb1 = 32.0f * __ldg(b2g + col + 1);
            #pragma unroll
            for (int m = 0; m < 2; ++m) {
                int r0 = 16 * m + gid;
                float2 s0 = *(float2*)(Os1 + r0 * DDIM + col);
                float2 s1 = *(float2*)(Os1 + (r0 + 8) * DDIM + col);
                float2 u0 = *(float2*)(Os2 + r0 * DDIM + col);
                float2 u1 = *(float2*)(Os2 + (r0 + 8) * DDIM + col);
                *(float2*)(og + (size_t)r0 * DDIM + col) =
                    make_float2(oacc[m][t][0] + s0.x + u0.x + bb0,
                                oacc[m][t][1] + s0.y + u0.y + bb1);
                *(float2*)(og + (size_t)(r0 + 8) * DDIM + col) =
                    make_float2(oacc[m][t][2] + s1.x + u1.x + bb0,
                                oacc[m][t][3] + s1.y + u1.y + bb1);
            }
        }
    }
}

extern "C" void kernel_launch(void* const* d_in, const int* in_sizes, int n_in,
                              void* d_out, int out_size) {
    (void)in_sizes; (void)n_in; (void)out_size;
    const float* X  = (const float*)d_in[0];   // [128,32,256]
    const float* W1 = (const float*)d_in[1];   // [256,1024]
    const float* b1 = (const float*)d_in[2];   // [1024]
    const float* W2 = (const float*)d_in[3];   // [1024,256]
    const float* b2 = (const float*)d_in[4];   // [256]
    float* out = (float*)d_out;                // [128,32,256]

    cudaFuncSetAttribute(fused_pair_mlp_v8,
                         cudaFuncAttributeMaxDynamicSharedMemorySize, SMEM_TOTAL);
    fused_pair_mlp_v8<<<128, THREADS, SMEM_TOTAL>>>(X, W1, b1, W2, b2, out);
}

// round 17
// speedup vs baseline: 1.6234x; 1.0059x over previous
#include <cuda_runtime.h>
#include <cuda_fp16.h>
#include <cstdint>

#define NDIM   32
#define DDIM   256
#define HDIM   1024
#define HC     128
#define NCHUNK 8
#define THREADS 384
#define NGROUP 3

// strides in halves (R5-proven conflict-free classes)
#define XH_H 264
#define PS_H 264
#define W1_H 136
#define W2_H 264
#define HS_H 136

// byte offsets
#define S_XH  0                      // fp16 [32][264]            16896
#define S_PS  16896                  // 3 x fp16 [32][264]        50688
#define PS_BUF 16896
#define S_W1  67584                  // fp16 [256][136]           69632
#define S_W2  137216                 // fp16 [128][264]           67584
#define S_HS  204800                 // 3 x fp16 [32][136]        26112
#define HS_BUF 8704
#define SMEM_TOTAL 230912

// prepped fp16 weights, laid out in per-chunk staging order (contiguous)
__device__ __half g_W1p[NCHUNK * 256 * 128];   // [c][d 0..255][f 0..127]
__device__ __half g_W2p[NCHUNK * 128 * 256];   // [c][h 0..127][f 0..255]

__device__ __forceinline__ unsigned smem_u32(const void* p) {
    unsigned a;
    asm("{ .reg .u64 t; cvta.to.shared.u64 t, %1; cvt.u32.u64 %0, t; }" : "=r"(a) : "l"(p));
    return a;
}
__device__ __forceinline__ void cpa16(unsigned dst, const void* src) {
    asm volatile("cp.async.cg.shared.global [%0], [%1], 16;\n" :: "r"(dst), "l"(src));
}
__device__ __forceinline__ void ldsm4(unsigned r[4], unsigned a) {
    asm volatile("ldmatrix.sync.aligned.m8n8.x4.shared.b16 {%0,%1,%2,%3}, [%4];\n"
                 : "=r"(r[0]), "=r"(r[1]), "=r"(r[2]), "=r"(r[3]) : "r"(a));
}
__device__ __forceinline__ void ldsm4t(unsigned r[4], unsigned a) {
    asm volatile("ldmatrix.sync.aligned.m8n8.x4.trans.shared.b16 {%0,%1,%2,%3}, [%4];\n"
                 : "=r"(r[0]), "=r"(r[1]), "=r"(r[2]), "=r"(r[3]) : "r"(a));
}
__device__ __forceinline__ void mma16816(float d[4], const unsigned a[4],
                                         unsigned b0, unsigned b1) {
    asm volatile("mma.sync.aligned.m16n8k16.row.col.f32.f16.f16.f32 "
                 "{%0,%1,%2,%3}, {%4,%5,%6,%7}, {%8,%9}, {%0,%1,%2,%3};\n"
                 : "+f"(d[0]), "+f"(d[1]), "+f"(d[2]), "+f"(d[3])
                 : "r"(a[0]), "r"(a[1]), "r"(a[2]), "r"(a[3]), "r"(b0), "r"(b1));
}
__device__ __forceinline__ unsigned hmul2u(unsigned a, unsigned b) {
    __half2 r = __hmul2(*(__half2*)&a, *(__half2*)&b);
    return *(unsigned*)&r;
}
__device__ __forceinline__ unsigned f2h2u(float x, float y) {
    __half2 h = __floats2half2_rn(x, y);
    return *(unsigned*)&h;
}

// ---- one-time weight convert (same RN converts as before, just hoisted) ----
__global__ void prep_weights(const float* __restrict__ W1, const float* __restrict__ W2) {
    int idx = blockIdx.x * blockDim.x + threadIdx.x;   // 0..65535, 4 halves each
    int e = idx * 4;
    {
        int c = e >> 15, r = (e >> 7) & 255, f = e & 127;
        float4 v = *(const float4*)(W1 + r * HDIM + c * HC + f);
        *(uint2*)(g_W1p + e) = make_uint2(f2h2u(v.x, v.y), f2h2u(v.z, v.w));
    }
    {
        int c = e >> 15, h = (e >> 8) & 127, f = e & 255;
        float4 v = *(const float4*)(W2 + (size_t)(c * HC + h) * DDIM + f);
        *(uint2*)(g_W2p + e) = make_uint2(f2h2u(v.x, v.y), f2h2u(v.z, v.w));
    }
}

__global__ __launch_bounds__(THREADS, 1)
void fused_pair_mlp_v9(const float* __restrict__ X,
                       const float* __restrict__ b1g,
                       const float* __restrict__ b2g, float* __restrict__ out)
{
    extern __shared__ unsigned char smem[];
    const int b = blockIdx.x, tid = threadIdx.x;
    const int w = tid >> 5, lane = tid & 31;
    const int g = w >> 2;          // 3 groups of 4 warps
    const int wg = w & 3;
    const int gtid = tid & 127;    // thread-in-group
    const int gid = lane >> 2, tig = lane & 3;

    unsigned char* Psp = smem + S_PS + g * PS_BUF;
    unsigned char* W1p = smem + S_W1;
    unsigned char* W2p = smem + S_W2;
    unsigned char* Hsp = smem + S_HS + g * HS_BUF;
    const unsigned uW1 = smem_u32(W1p), uW2 = smem_u32(W2p);

    // ---- stage X_b as fp16 [32][264]
    for (int q = tid; q < 1024; q += THREADS) {
        int row = q >> 5, u = q & 31;
        const float4* s = (const float4*)(X + (size_t)b * 8192 + row * 256 + u * 8);
        float4 v0 = s[0], v1 = s[1];
        *(uint4*)(smem + S_XH + row * 528 + u * 16) =
            make_uint4(f2h2u(v0.x, v0.y), f2h2u(v0.z, v0.w),
                       f2h2u(v1.x, v1.y), f2h2u(v1.z, v1.w));
    }

    // ldmatrix per-lane address components (R5-identical)
    const int mat  = lane >> 3, mr = lane & 7;
    const int lrow = (mat & 1) * 8 + mr;
    const int kh   = (mat >> 1) * 8;

    const unsigned aA  = smem_u32(Psp) + (unsigned)(lrow * PS_H + kh) * 2u;
    const unsigned aB1 = uW1 + (unsigned)(lrow * W1_H + 32 * wg + kh) * 2u;
    const unsigned aH  = smem_u32(Hsp) + (unsigned)(lrow * HS_H + kh) * 2u;
    const unsigned aB2 = uW2 + (unsigned)(lrow * W2_H + 64 * wg + kh) * 2u;

    // P-build mapping (conflict-free): row = lane, 128B slice = warp-in-group
    const int pj = lane, ps = gtid >> 5;

    // persistent out accumulator: warp owns out cols [64wg, 64wg+64)
    float oacc[2][8][4];
    #pragma unroll
    for (int m = 0; m < 2; ++m)
        #pragma unroll
        for (int t = 0; t < 8; ++t)
            #pragma unroll
            for (int r = 0; r < 4; ++r) oacc[m][t][r] = 0.f;

    for (int c = 0; c < NCHUNK; ++c) {
        __syncthreads();  // all readers of previous W chunk done

        // ---- async-stage W1 chunk [256 d][128 hc] (pure 16B copies)
        {
            const __half* src = g_W1p + c * 32768;
            for (int q = tid; q < 4096; q += THREADS) {
                int d = q >> 4, f = q & 15;
                cpa16(uW1 + (unsigned)(d * 272 + f * 16), src + q * 8);
            }
        }
        // ---- async-stage W2 chunk [128 hc][256 d]
        {
            const __half* src = g_W2p + c * 32768;
            for (int q = tid; q < 4096; q += THREADS) {
                int h = q >> 5, f = q & 31;
                cpa16(uW2 + (unsigned)(h * 528 + f * 16), src + q * 8);
            }
        }
        float b1v[4][2];
        #pragma unroll
        for (int t = 0; t < 4; ++t) {
            b1v[t][0] = __ldg(b1g + c * HC + 32 * wg + 8 * t + 2 * tig);
            b1v[t][1] = __ldg(b1g + c * HC + 32 * wg + 8 * t + 2 * tig + 1);
        }
        asm volatile("cp.async.commit_group;\n" ::: "memory");
        asm volatile("cp.async.wait_group 0;\n" ::: "memory");
        __syncthreads();  // W chunk ready (cp.async drained by all threads)

        for (int ii = 0; ii < 11; ++ii) {
            const int i = NGROUP * ii + g;   // group-private i stream
            if (i < NDIM) {
                // ---- build P_i[j,:] = xh[j] .* xh[i]  (conflict-free mapping)
                {
                    const unsigned char* xj = smem + S_XH + pj * 528 + ps * 128;
                    const unsigned char* xi = smem + S_XH + i * 528 + ps * 128;
                    unsigned char* pd = Psp + pj * 528 + ps * 128;
                    #pragma unroll
                    for (int k = 0; k < 8; ++k) {
                        uint4 a  = *(const uint4*)(xj + k * 16);
                        uint4 c2 = *(const uint4*)(xi + k * 16);
                        uint4 o;
                        o.x = hmul2u(a.x, c2.x); o.y = hmul2u(a.y, c2.y);
                        o.z = hmul2u(a.z, c2.z); o.w = hmul2u(a.w, c2.w);
                        *(uint4*)(pd + k * 16) = o;
                    }
                }
                asm volatile("bar.sync %0, %1;" :: "r"(1 + g), "r"(128));  // P ready

                // ---- GEMM1: h[32, 32wg..+32] = P[32,256] @ W1[256, chunk]
                float hacc[2][4][4];
                #pragma unroll
                for (int m = 0; m < 2; ++m)
                    #pragma unroll
                    for (int t = 0; t < 4; ++t)
                        #pragma unroll
                        for (int r = 0; r < 4; ++r) hacc[m][t][r] = 0.f;
                #pragma unroll 2
                for (int kk = 0; kk < 16; ++kk) {
                    unsigned A0[4], A1[4], B[8];
                    unsigned ak = aA + (unsigned)(kk * 32);
                    ldsm4(A0, ak);
                    ldsm4(A1, ak + (unsigned)(16 * 528));
                    unsigned bk = aB1 + (unsigned)(kk * 16 * 272);
                    ldsm4t(B, bk);
                    ldsm4t(B + 4, bk + 32);
                    #pragma unroll
                    for (int t = 0; t < 4; ++t) {
                        mma16816(hacc[0][t], A0, B[2 * t], B[2 * t + 1]);
                        mma16816(hacc[1][t], A1, B[2 * t], B[2 * t + 1]);
                    }
                }

                // ---- bias + relu -> Hs (single buffer; safe by barrier order)
                #pragma unroll
                for (int m = 0; m < 2; ++m) {
                    #pragma unroll
                    for (int t = 0; t < 4; ++t) {
                        int col = 32 * wg + 8 * t + 2 * tig;
                        float f0 = fmaxf(hacc[m][t][0] + b1v[t][0], 0.f);
                        float f1 = fmaxf(hacc[m][t][1] + b1v[t][1], 0.f);
                        float f2 = fmaxf(hacc[m][t][2] + b1v[t][0], 0.f);
                        float f3 = fmaxf(hacc[m][t][3] + b1v[t][1], 0.f);
                        int r0 = 16 * m + gid;
                        *(unsigned*)(Hsp + r0 * 272 + col * 2)       = f2h2u(f0, f1);
                        *(unsigned*)(Hsp + (r0 + 8) * 272 + col * 2) = f2h2u(f2, f3);
                    }
                }
                asm volatile("bar.sync %0, %1;" :: "r"(1 + g), "r"(128));  // Hs ready

                // ---- GEMM2: oacc[32, 64wg..] += h[32,128] @ W2[128,256]
                #pragma unroll 2
                for (int kk = 0; kk < 8; ++kk) {
                    unsigned A0[4], A1[4], B[8];
                    unsigned ak = aH + (unsigned)(kk * 32);
                    ldsm4(A0, ak);
                    ldsm4(A1, ak + (unsigned)(16 * 272));
                    unsigned bk = aB2 + (unsigned)(kk * 16 * 528);
                    ldsm4t(B, bk);
                    ldsm4t(B + 4, bk + 32);
                    #pragma unroll
                    for (int t = 0; t < 4; ++t) {
                        mma16816(oacc[0][t], A0, B[2 * t], B[2 * t + 1]);
                        mma16816(oacc[1][t], A1, B[2 * t], B[2 * t + 1]);
                    }
                    ldsm4t(B, bk + 64);
                    ldsm4t(B + 4, bk + 96);
                    #pragma unroll
                    for (int t = 0; t < 4; ++t) {
                        mma16816(oacc[0][t + 4], A0, B[2 * t], B[2 * t + 1]);
                        mma16816(oacc[1][t + 4], A1, B[2 * t], B[2 * t + 1]);
                    }
                }
            }
        }
    }

    // ---- epilogue: groups 1,2 dump to smem; group 0 reduces + bias + store
    __syncthreads();
    if (g > 0) {
        float* Os = (float*)(smem + (g - 1) * 32768);   // X/P regions dead
        #pragma unroll
        for (int t = 0; t < 8; ++t) {
            int col = 64 * wg + 8 * t + 2 * tig;
            #pragma unroll
            for (int m = 0; m < 2; ++m) {
                int r0 = 16 * m + gid;
                *(float2*)(Os + r0 * DDIM + col)       = make_float2(oacc[m][t][0], oacc[m][t][1]);
                *(float2*)(Os + (r0 + 8) * DDIM + col) = make_float2(oacc[m][t][2], oacc[m][t][3]);
            }
        }
    }
    __syncthreads();
    if (g == 0) {
        float* Os1 = (float*)(smem);
        float* Os2 = (float*)(smem + 32768);
        float* og = out + (size_t)b * NDIM * DDIM;
        #pragma unroll
        for (int t = 0; t < 8; ++t) {
            int col = 64 * wg + 8 * t + 2 * tig;
            float bb0 = 32.0f * __ldg(b2g + col);
            float bb1 = 32.0f * __ldg(b2g + col + 1);
            #pragma unroll
            for (int m = 0; m < 2; ++m) {
                int r0 = 16 * m + gid;
                float2 s0 = *(float2*)(Os1 + r0 * DDIM + col);
                float2 s1 = *(float2*)(Os1 + (r0 + 8) * DDIM + col);
                float2 u0 = *(float2*)(Os2 + r0 * DDIM + col);
                float2 u1 = *(float2*)(Os2 + (r0 + 8) * DDIM + col);
                *(float2*)(og + (size_t)r0 * DDIM + col) =
                    make_float2(oacc[m][t][0] + s0.x + u0.x + bb0,
                                oacc[m][t][1] + s0.y + u0.y + bb1);
                *(float2*)(og + (size_t)(r0 + 8) * DDIM + col) =
                    make_float2(oacc[m][t][2] + s1.x + u1.x + bb0,
                                oacc[m][t][3] + s1.y + u1.y + bb1);
            }
        }
    }
}

extern "C" void kernel_launch(void* const* d_in, const int* in_sizes, int n_in,
                              void* d_out, int out_size) {
    (void)in_sizes; (void)n_in; (void)out_size;
    const float* X  = (const float*)d_in[0];   // [128,32,256]
    const float* W1 = (const float*)d_in[1];   // [256,1024]
    const float* b1 = (const float*)d_in[2];   // [1024]
    const float* W2 = (const float*)d_in[3];   // [1024,256]
    const float* b2 = (const float*)d_in[4];   // [256]
    float* out = (float*)d_out;                // [128,32,256]

    prep_weights<<<256, 256>>>(W1, W2);
    cudaFuncSetAttribute(fused_pair_mlp_v9,
                         cudaFuncAttributeMaxDynamicSharedMemorySize, SMEM_TOTAL);
    fused_pair_mlp_v9<<<128, THREADS, SMEM_TOTAL>>>(X, b1, b2, out);
}